// round 7
// baseline (speedup 1.0000x reference)
#include <cuda_runtime.h>
#include <cuda_bf16.h>
#include <cstdint>

typedef unsigned long long u64;

#define BB 32
#define TT 256
#define II 128
#define HH 128
#define GG 512   // 4*H
#define CC 100
#define WS_PAD 132

// ---------------- scratch (device globals; no allocation allowed) ----------
__device__ float g_gatesx[TT * BB * GG];      // [t][b][g]
__device__ float g_hist[(TT + 1) * BB * HH];  // [j][b][u], j=1..256 = h_1..h_256
__device__ float g_attn[BB * HH];
__device__ float g_q[BB * HH];                // q = h_T @ w1_top

__device__ __forceinline__ void fma2(u64 &acc, u64 a, u64 b) {
    asm("fma.rn.f32x2 %0, %1, %2, %0;" : "+l"(acc) : "l"(a), "l"(b));
}
__device__ __forceinline__ float sum2(u64 v) {
    float lo, hi;
    asm("mov.b64 {%0,%1}, %2;" : "=f"(lo), "=f"(hi) : "l"(v));
    return lo + hi;
}
// fast activations via MUFU ex2 (~1e-7 abs error, fine vs 1e-3 gate)
__device__ __forceinline__ float fast_sig(float x) {
    return __fdividef(1.0f, 1.0f + __expf(-x));
}
__device__ __forceinline__ float fast_tanh(float x) {
    return fmaf(-2.0f, __fdividef(1.0f, __expf(2.0f * x) + 1.0f), 1.0f);
}
__device__ __forceinline__ uint32_t smem_u32(const void* p) {
    uint32_t a;
    asm("{ .reg .u64 t; cvta.to.shared.u64 t, %1; cvt.u32.u64 %0, t; }" : "=r"(a) : "l"(p));
    return a;
}

// ---------------------------------------------------------------------------
// Phase 1: gates_x[t][b][g] = x[b,t,:] . w_ih[g,:] + b_ih[g] + b_hh[g]
// grid (T, 4) x 256 threads.
// ---------------------------------------------------------------------------
__global__ void __launch_bounds__(256, 2) phase1_kernel(
    const float* __restrict__ x, const float* __restrict__ w_ih,
    const float* __restrict__ b_ih, const float* __restrict__ b_hh)
{
    extern __shared__ float sm[];
    float* x_s = sm;                 // [32][128]
    float* ws  = sm + BB * II;       // [128][WS_PAD]
    const int t   = blockIdx.x;
    const int gq  = blockIdx.y;      // 0..3: which 128-gate tile
    const int tid = threadIdx.x;

    for (int i = tid; i < BB * II; i += 256) {
        int b = i >> 7, k = i & 127;
        x_s[i] = x[(b * TT + t) * II + k];
    }
    const float* wsrc = w_ih + gq * 128 * II;
    for (int i = tid; i < 128 * II; i += 256) {
        int gl = i >> 7, k = i & 127;
        ws[gl * WS_PAD + k] = wsrc[i];
    }
    if (t == 0 && gq == 0) {   // re-zero attention accumulator every launch
        for (int i = tid; i < BB * HH; i += 256) g_attn[i] = 0.0f;
    }
    __syncthreads();

    const int gl   = tid & 127;
    const int half = tid >> 7;
    const int g    = gq * 128 + gl;
    const float bias = b_ih[g] + b_hh[g];
    const float* wrow = ws + gl * WS_PAD;

    for (int bq = 0; bq < 2; bq++) {
        const int b0 = half * 16 + bq * 8;
        u64 acc[8];
        #pragma unroll
        for (int j = 0; j < 8; j++) acc[j] = 0ull;
        #pragma unroll
        for (int k0 = 0; k0 < II; k0 += 4) {
            ulonglong2 w = *(const ulonglong2*)(wrow + k0);
            #pragma unroll
            for (int j = 0; j < 8; j++) {
                ulonglong2 xv = *(const ulonglong2*)(x_s + (b0 + j) * II + k0);
                fma2(acc[j], w.x, xv.x);
                fma2(acc[j], w.y, xv.y);
            }
        }
        #pragma unroll
        for (int j = 0; j < 8; j++)
            g_gatesx[(t * BB + b0 + j) * GG + g] = sum2(acc[j]) + bias;
    }
}

// ---------------------------------------------------------------------------
// Phase 2: LSTM recurrence on a 2-CTA cluster per batch element.
// grid = 64 CTAs (cluster pairs), 256 threads each.
//   b = blockIdx.x >> 1, rank = ctarank (0/1).
//   thread tid: gate gi = tid>>6 (0:i 1:f 2:g 3:o), unit u = rank*64 + (tid&63)
//   -> global row = gi*128 + u. ALL 64 weight pairs of the row in registers.
// h exchange: local smem (double-buffered) + DSMEM store to peer + 64-arrival
// mbarrier (release/acquire, parity = t&1).
// ---------------------------------------------------------------------------
__global__ void __launch_bounds__(256, 1) __cluster_dims__(2, 1, 1)
phase2_kernel(const float* __restrict__ w_hh)
{
    __shared__ __align__(16) float h_buf[2][HH];
    __shared__ float act_s[256];
    __shared__ __align__(8) u64 mbar[1];

    uint32_t rank;
    asm("mov.u32 %0, %%cluster_ctarank;" : "=r"(rank));
    const int b   = blockIdx.x >> 1;
    const int tid = threadIdx.x;
    const int gi  = tid >> 6;          // 0:i 1:f 2:g 3:o
    const int ul  = tid & 63;
    const int u   = (int)rank * 64 + ul;
    const int row = gi * HH + u;

    // row weights fully register-resident: 64 u64 pairs = 128 regs
    const float* wrow = w_hh + row * HH;
    u64 wr[64];
    #pragma unroll
    for (int i = 0; i < 64; i++) wr[i] = *(const u64*)(wrow + 2 * i);

    const uint32_t mbar_a = smem_u32(&mbar[0]);
    if (tid == 0) {
        asm volatile("mbarrier.init.shared.b64 [%0], %1;" :: "r"(mbar_a), "r"(64) : "memory");
    }
    if (tid < 2 * HH) ((float*)h_buf)[tid] = 0.0f;
    __syncthreads();
    asm volatile("barrier.cluster.arrive.aligned;" ::: "memory");
    asm volatile("barrier.cluster.wait.aligned;"   ::: "memory");

    // peer addresses (computed once)
    const uint32_t h_a = smem_u32(&h_buf[0][0]);
    uint32_t peer_h, peer_mbar;
    asm("mapa.shared::cluster.u32 %0, %1, %2;" : "=r"(peer_h)    : "r"(h_a),    "r"(rank ^ 1u));
    asm("mapa.shared::cluster.u32 %0, %1, %2;" : "=r"(peer_mbar) : "r"(mbar_a), "r"(rank ^ 1u));

    float c = 0.0f;
    const int stride_t = BB * GG;
    const float* gxp = g_gatesx + b * GG + row;
    float gxn = gxp[0];

    for (int t = 0; t < TT; t++) {
        const int p = t & 1;
        float gx = gxn;
        if (t + 1 < TT) gxn = gxp[(t + 1) * stride_t];

        const ulonglong2* h4 = (const ulonglong2*)&h_buf[p][0];  // 32 chunks, broadcast
        u64 a0 = 0ull, a1 = 0ull;
        #pragma unroll
        for (int i = 0; i < 32; i++) {
            ulonglong2 hv = h4[i];
            fma2(a0, wr[2 * i],     hv.x);
            fma2(a1, wr[2 * i + 1], hv.y);
        }

        float gate = gx + sum2(a0) + sum2(a1);
        float a = (gi == 2) ? fast_tanh(gate) : fast_sig(gate);
        act_s[tid] = a;
        __syncthreads();                     // act_s ready; h_buf[p] reads done

        if (gi == 0) {
            float af = act_s[64 + ul];
            float ag = act_s[128 + ul];
            float ao = act_s[192 + ul];
            c = af * c + a * ag;             // sig(f)*c + sig(i)*tanh(g)
            float hv = ao * fast_tanh(c);
            h_buf[1 - p][u] = hv;            // local half
            asm volatile("st.shared::cluster.f32 [%0], %1;"
                         :: "r"(peer_h + (uint32_t)(((1 - p) * HH + u) * 4)), "f"(hv)
                         : "memory");        // peer half via DSMEM
            g_hist[(t + 1) * (BB * HH) + b * HH + u] = hv;
            asm volatile("mbarrier.arrive.release.cluster.shared::cluster.b64 _, [%0];"
                         :: "r"(peer_mbar) : "memory");
        }
        __syncthreads();                     // local h_buf[1-p] visible

        // wait for peer's 64 arrivals (phase parity = t&1), acquire cluster
        {
            uint32_t done;
            asm volatile(
                "{\n\t"
                ".reg .pred q;\n\t"
                "mbarrier.try_wait.parity.acquire.cluster.shared::cta.b64 q, [%1], %2;\n\t"
                "selp.b32 %0, 1, 0, q;\n\t"
                "}" : "=r"(done) : "r"(mbar_a), "r"((uint32_t)(t & 1)) : "memory");
            if (!done) {
                asm volatile(
                    "{\n\t"
                    ".reg .pred q;\n\t"
                    "WL_%=:\n\t"
                    "mbarrier.try_wait.parity.acquire.cluster.shared::cta.b64 q, [%0], %1, 0x989680;\n\t"
                    "@q bra.uni WD_%=;\n\t"
                    "bra.uni WL_%=;\n\t"
                    "WD_%=:\n\t"
                    "}" :: "r"(mbar_a), "r"((uint32_t)(t & 1)) : "memory");
            }
        }
    }

    asm volatile("barrier.cluster.arrive.aligned;" ::: "memory");
    asm volatile("barrier.cluster.wait.aligned;"   ::: "memory");
}

// ---------------------------------------------------------------------------
// Phase q: g_q[b][n] = sum_k h_T[k] * w1[k][n]   (w1 top half)
// ---------------------------------------------------------------------------
__global__ void __launch_bounds__(128, 8) phaseq_kernel(const float* __restrict__ w1)
{
    __shared__ float hf[HH];
    const int b = blockIdx.x, n = threadIdx.x;
    hf[n] = g_hist[TT * (BB * HH) + b * HH + n];
    __syncthreads();
    float q = 0.0f;
    #pragma unroll 4
    for (int k = 0; k < HH; k++) q += hf[k] * w1[k * HH + n];
    g_q[b * HH + n] = q;
}

// ---------------------------------------------------------------------------
// Phase 3a: final attention over memory h_1..h_255.
//   p_j[n] = sum_k h_j[k] * w1[H+k][n]
//   s_j    = sum_n w2[n] * tanh(q[b][n] + p_j[n])
//   attn[b][n] += sum_j s_j * h_j[n]
// grid (B, 8) x 256 threads; each block covers 32 j's in 4 tiles of 8.
// ---------------------------------------------------------------------------
__global__ void __launch_bounds__(256, 1) phase3a_kernel(
    const float* __restrict__ w1, const float* __restrict__ w2)
{
    extern __shared__ float sm[];
    float* ws   = sm;                        // [128][WS_PAD]  (w1 bottom)
    float* w2_s = ws + 128 * WS_PAD;         // [128]
    float* hj_s = w2_s + 128;                // [8][128]
    float* red  = hj_s + 8 * 128;            // [8][4]
    float* s_t  = red + 32;                  // [8]
    const int b   = blockIdx.x;
    const int jc  = blockIdx.y;
    const int tid = threadIdx.x;
    const int n    = tid & 127;
    const int half = tid >> 7;
    const int lane = tid & 31;
    const int wl   = (tid >> 5) & 3;

    const float* w1b = w1 + HH * HH;         // bottom half
    for (int i = tid; i < HH * HH; i += 256) {
        int k = i >> 7, kk = i & 127;
        ws[k * WS_PAD + kk] = w1b[i];
    }
    if (tid < 128) w2_s[tid] = w2[tid];
    __syncthreads();

    const float q   = g_q[b * HH + n];
    const float w2n = w2_s[n];

    float accA = 0.0f;
    const int j0 = 1 + jc * 32;
    const int jb = half * 4;
    const float* wb = ws + n;

    for (int tile = 0; tile < 4; tile++) {
        int jt = j0 + tile * 8;
        for (int r = 0; r < 4; r++) {
            int lin = r * 256 + tid;
            int jj = lin >> 7, k = lin & 127;
            int j = jt + jj;
            hj_s[jj * 128 + k] = (j <= TT - 1) ? g_hist[j * (BB * HH) + b * HH + k] : 0.0f;
        }
        __syncthreads();

        float p0 = 0, p1 = 0, p2 = 0, p3 = 0;
        #pragma unroll 4
        for (int k = 0; k < HH; k++) {
            float w = wb[k * WS_PAD];
            p0 += hj_s[(jb + 0) * 128 + k] * w;
            p1 += hj_s[(jb + 1) * 128 + k] * w;
            p2 += hj_s[(jb + 2) * 128 + k] * w;
            p3 += hj_s[(jb + 3) * 128 + k] * w;
        }
        float sv[4];
        sv[0] = w2n * fast_tanh(q + p0);
        sv[1] = w2n * fast_tanh(q + p1);
        sv[2] = w2n * fast_tanh(q + p2);
        sv[3] = w2n * fast_tanh(q + p3);
        #pragma unroll
        for (int jj = 0; jj < 4; jj++) {
            float v = sv[jj];
            v += __shfl_down_sync(0xffffffffu, v, 16);
            v += __shfl_down_sync(0xffffffffu, v, 8);
            v += __shfl_down_sync(0xffffffffu, v, 4);
            v += __shfl_down_sync(0xffffffffu, v, 2);
            v += __shfl_down_sync(0xffffffffu, v, 1);
            if (lane == 0) red[(half * 4 + jj) * 4 + wl] = v;
        }
        __syncthreads();
        if (tid < 8)
            s_t[tid] = red[tid * 4 + 0] + red[tid * 4 + 1] + red[tid * 4 + 2] + red[tid * 4 + 3];
        __syncthreads();

        accA += s_t[jb + 0] * hj_s[(jb + 0) * 128 + n]
              + s_t[jb + 1] * hj_s[(jb + 1) * 128 + n]
              + s_t[jb + 2] * hj_s[(jb + 2) * 128 + n]
              + s_t[jb + 3] * hj_s[(jb + 3) * 128 + n];
        __syncthreads();   // protect hj_s / red / s_t before next tile
    }
    atomicAdd(&g_attn[b * HH + n], accA);
}

// ---------------------------------------------------------------------------
// Phase 3b: out[b] = (h_T + attn[b]) @ w_fc^T + b_fc      (32 x 100 output)
// ---------------------------------------------------------------------------
__global__ void __launch_bounds__(128, 8) phase3b_kernel(
    const float* __restrict__ w_fc, const float* __restrict__ b_fc,
    float* __restrict__ out)
{
    __shared__ float v_s[HH];
    const int b = blockIdx.x, tid = threadIdx.x;
    v_s[tid] = g_hist[TT * (BB * HH) + b * HH + tid] + g_attn[b * HH + tid];
    __syncthreads();
    if (tid < CC) {
        float acc = b_fc[tid];
        const float4* wr4 = (const float4*)(w_fc + tid * HH);
        const float4* v4  = (const float4*)v_s;
        #pragma unroll
        for (int k4 = 0; k4 < HH / 4; k4++) {
            float4 w = wr4[k4];
            float4 v = v4[k4];
            acc += w.x * v.x + w.y * v.y + w.z * v.z + w.w * v.w;
        }
        out[b * CC + tid] = acc;
    }
}

// ---------------------------------------------------------------------------
extern "C" void kernel_launch(void* const* d_in, const int* in_sizes, int n_in,
                              void* d_out, int out_size)
{
    const float* x    = (const float*)d_in[0];
    const float* w_ih = (const float*)d_in[1];
    const float* b_ih = (const float*)d_in[2];
    const float* w_hh = (const float*)d_in[3];
    const float* b_hh = (const float*)d_in[4];
    const float* w1   = (const float*)d_in[5];
    const float* w2   = (const float*)d_in[6];
    const float* w_fc = (const float*)d_in[7];
    const float* b_fc = (const float*)d_in[8];
    float* out = (float*)d_out;

    const int SM1 = (BB * II + 128 * WS_PAD) * (int)sizeof(float);                // ~84 KB
    const int SM3 = (128 * WS_PAD + 128 + 8 * 128 + 32 + 8) * (int)sizeof(float); // ~72.4 KB

    cudaFuncSetAttribute(phase1_kernel,  cudaFuncAttributeMaxDynamicSharedMemorySize, SM1);
    cudaFuncSetAttribute(phase3a_kernel, cudaFuncAttributeMaxDynamicSharedMemorySize, SM3);

    phase1_kernel <<<dim3(TT, 4), 256, SM1>>>(x, w_ih, b_ih, b_hh);
    phase2_kernel <<<2 * BB, 256>>>(w_hh);
    phaseq_kernel <<<BB, HH>>>(w1);
    phase3a_kernel<<<dim3(BB, 8), 256, SM3>>>(w1, w2);
    phase3b_kernel<<<BB, HH>>>(w_fc, b_fc, out);
}